// round 2
// baseline (speedup 1.0000x reference)
#include <cuda_runtime.h>
#include <math.h>

#define BATCH 4096
#define DIM   768
#define NCLS  10

#define BM 128
#define BN 128
#define BK 16
#define NT (BATCH / BM)          // 32 tiles per side
#define NBLK (NT * (NT + 1) / 2) // 528 upper-triangular tiles

__device__ __forceinline__ int clampc(int v) {
    return v < 0 ? 0 : (v >= NCLS ? NCLS - 1 : v);
}

// ---------------- scratch (no allocations allowed) ----------------
__device__ float g_enorm[BATCH * DIM];   // normalized embeddings
__device__ float g_cents_sum[NCLS * DIM];
__device__ float g_counts[NCLS];
__device__ float g_ce_sum;
__device__ float g_taml_sum;
__device__ float g_tals;

// ---------------- init: zero accumulators ----------------
__global__ void k_init() {
    int tid = threadIdx.x;
    for (int i = tid; i < NCLS * DIM; i += blockDim.x) g_cents_sum[i] = 0.0f;
    if (tid < NCLS) g_counts[tid] = 0.0f;
    if (tid == 0) { g_ce_sum = 0.0f; g_taml_sum = 0.0f; g_tals = 0.0f; }
}

// ---------------- CE + row normalization ----------------
// 8 warps per block, one warp per row. 512 blocks.
__global__ __launch_bounds__(256) void k_ce_norm(
    const float* __restrict__ logits,
    const int* __restrict__ labels,
    const float* __restrict__ emb)
{
    const unsigned FULL = 0xffffffffu;
    int warp = threadIdx.x >> 5;
    int lane = threadIdx.x & 31;
    int row  = blockIdx.x * 8 + warp;

    const float* e = emb + (size_t)row * DIM;
    float v[DIM / 32];
    float ss = 0.0f;
#pragma unroll
    for (int i = 0; i < DIM / 32; i++) {
        v[i] = e[lane + 32 * i];
        ss += v[i] * v[i];
    }
#pragma unroll
    for (int o = 16; o; o >>= 1) ss += __shfl_xor_sync(FULL, ss, o);
    float inv = 1.0f / fmaxf(sqrtf(ss), 1e-12f);
    float* outp = g_enorm + (size_t)row * DIM;
#pragma unroll
    for (int i = 0; i < DIM / 32; i++) outp[lane + 32 * i] = v[i] * inv;

    // cross entropy for this row (10 classes handled by lanes 0..9)
    int lab = clampc(labels[row]);
    float lg = (lane < NCLS) ? logits[row * NCLS + lane] : -INFINITY;
    float m = lg;
#pragma unroll
    for (int o = 16; o; o >>= 1) m = fmaxf(m, __shfl_xor_sync(FULL, m, o));
    float p = (lane < NCLS) ? expf(lg - m) : 0.0f;
    float s = p;
#pragma unroll
    for (int o = 16; o; o >>= 1) s += __shfl_xor_sync(FULL, s, o);
    float lse = logf(s) + m;
    float target = __shfl_sync(FULL, lg, lab);
    if (lane == 0) {
        atomicAdd(&g_ce_sum, lse - target);
        atomicAdd(&g_counts[lab], 1.0f);
    }
}

// ---------------- per-class centroid sums ----------------
// grid (3, 8): blockIdx.x selects 256 columns, blockIdx.y selects 512 rows.
__global__ __launch_bounds__(256) void k_centsum(
    const float* __restrict__ emb,
    const int* __restrict__ labels)
{
    __shared__ float acc[NCLS * 256];
    int tid = threadIdx.x;
#pragma unroll
    for (int c = 0; c < NCLS; c++) acc[c * 256 + tid] = 0.0f;
    __syncthreads();

    int col = blockIdx.x * 256 + tid;
    int r0  = blockIdx.y * 512;
#pragma unroll 4
    for (int r = r0; r < r0 + 512; r++) {
        int lab = clampc(labels[r]);
        acc[lab * 256 + tid] += emb[(size_t)r * DIM + col];
    }
    __syncthreads();
#pragma unroll
    for (int c = 0; c < NCLS; c++)
        atomicAdd(&g_cents_sum[c * DIM + col], acc[c * 256 + tid]);
}

// ---------------- TALS (single block) ----------------
__global__ __launch_bounds__(256) void k_tals(const float* __restrict__ topo) {
    __shared__ float sc[NCLS * DIM];   // centroids, 30 KB
    __shared__ float ed[NCLS * NCLS];
    int tid = threadIdx.x;

    for (int i = tid; i < NCLS * DIM; i += 256) {
        int c = i / DIM;
        float cnt = fmaxf(g_counts[c], 1.0f);
        sc[i] = g_cents_sum[i] / cnt;
    }
    __syncthreads();

    int warp = tid >> 5, lane = tid & 31;
    const unsigned FULL = 0xffffffffu;
    for (int p = warp; p < NCLS * NCLS; p += 8) {
        int i = p / NCLS, j = p % NCLS;
        float s = 0.0f;
        for (int d = lane; d < DIM; d += 32) {
            float df = sc[i * DIM + d] - sc[j * DIM + d];
            s += df * df;
        }
#pragma unroll
        for (int o = 16; o; o >>= 1) s += __shfl_xor_sync(FULL, s, o);
        if (lane == 0) ed[p] = sqrtf(s + 1e-12f);
    }
    __syncthreads();

    if (tid == 0) {
        float mx = 0.0f;
        for (int p = 0; p < NCLS * NCLS; p++) mx = fmaxf(mx, ed[p]);
        float inv = 1.0f / (mx + 1e-8f);
        float mse = 0.0f;
        for (int p = 0; p < NCLS * NCLS; p++) {
            float v = ed[p] * inv - topo[p];
            mse += v * v;
        }
        g_tals = mse / (float)(NCLS * NCLS);
    }
}

// ---------------- TAML: fused upper-triangular GEMM + margin reduce ----------
__global__ __launch_bounds__(256) void k_taml(
    const int* __restrict__ labels,
    const float* __restrict__ topo)
{
    __shared__ float As[BK][BM];
    __shared__ float Bs[BK][BN];
    __shared__ float sthr[NCLS * NCLS];
    __shared__ int   lrow[BM];
    __shared__ int   lcol[BN];
    __shared__ float sred[256];

    // decode upper-triangular tile (r <= c)
    int bid = blockIdx.x;
    int r = 0, rem = bid;
    while (rem >= (NT - r)) { rem -= (NT - r); r++; }
    int c = r + rem;

    int tid = threadIdx.x;
    if (tid < NCLS * NCLS) sthr[tid] = 1.0f - topo[tid];
    if (tid < BM) lrow[tid] = clampc(labels[r * BM + tid]);
    else if (tid < BM + BN) lcol[tid - BM] = clampc(labels[c * BN + (tid - BM)]);

    const float* Aptr = g_enorm + (size_t)(r * BM) * DIM;
    const float* Bptr = g_enorm + (size_t)(c * BN) * DIM;

    float acc[8][8];
#pragma unroll
    for (int i = 0; i < 8; i++)
#pragma unroll
        for (int j = 0; j < 8; j++) acc[i][j] = 0.0f;

    int tx = tid & 15, ty = tid >> 4;

    for (int kt = 0; kt < DIM; kt += BK) {
        __syncthreads();  // protect smem from previous iteration readers
#pragma unroll
        for (int q = 0; q < 2; q++) {
            int f  = tid + q * 256;
            int rr = f >> 2;
            int kk = (f & 3) * 4;
            float4 a = *(const float4*)(Aptr + (size_t)rr * DIM + kt + kk);
            As[kk + 0][rr] = a.x; As[kk + 1][rr] = a.y;
            As[kk + 2][rr] = a.z; As[kk + 3][rr] = a.w;
            float4 b = *(const float4*)(Bptr + (size_t)rr * DIM + kt + kk);
            Bs[kk + 0][rr] = b.x; Bs[kk + 1][rr] = b.y;
            Bs[kk + 2][rr] = b.z; Bs[kk + 3][rr] = b.w;
        }
        __syncthreads();
#pragma unroll
        for (int k = 0; k < BK; k++) {
            float a[8], b[8];
#pragma unroll
            for (int i = 0; i < 8; i++) a[i] = As[k][ty * 8 + i];
#pragma unroll
            for (int j = 0; j < 8; j++) b[j] = Bs[k][tx * 8 + j];
#pragma unroll
            for (int i = 0; i < 8; i++)
#pragma unroll
                for (int j = 0; j < 8; j++) acc[i][j] += a[i] * b[j];
        }
    }
    __syncthreads();

    // epilogue: relu margin sum. Off-diagonal tiles count twice (symmetry).
    float lsum = 0.0f;
#pragma unroll
    for (int i = 0; i < 8; i++) {
        int la = lrow[ty * 8 + i];
#pragma unroll
        for (int j = 0; j < 8; j++) {
            int lb = lcol[tx * 8 + j];
            if (la != lb) {
                float v = acc[i][j] - sthr[la * NCLS + lb];
                lsum += fmaxf(v, 0.0f);
            }
        }
    }
    if (r != c) lsum *= 2.0f;

    sred[tid] = lsum;
    __syncthreads();
    for (int s = 128; s > 0; s >>= 1) {
        if (tid < s) sred[tid] += sred[tid + s];
        __syncthreads();
    }
    if (tid == 0) atomicAdd(&g_taml_sum, sred[0]);
}

// ---------------- final combine ----------------
__global__ void k_final(float* __restrict__ out) {
    if (threadIdx.x == 0) {
        float s2 = 0.0f;
        for (int cc = 0; cc < NCLS; cc++) s2 += g_counts[cc] * g_counts[cc];
        float nvalid = (float)BATCH * (float)BATCH - s2;
        float taml = g_taml_sum / fmaxf(nvalid, 1.0f);
        float ce   = g_ce_sum / (float)BATCH;
        float tals = g_tals;
        out[0] = ce + 0.5f * tals + 0.5f * taml;
        out[1] = ce;
        out[2] = tals;
        out[3] = taml;
    }
}

extern "C" void kernel_launch(void* const* d_in, const int* in_sizes, int n_in,
                              void* d_out, int out_size) {
    const float* logits = (const float*)d_in[0];
    const int*   labels = (const int*)d_in[1];
    const float* emb    = (const float*)d_in[2];
    const float* topo   = (const float*)d_in[3];
    float* out = (float*)d_out;

    k_init<<<1, 1024>>>();
    k_ce_norm<<<BATCH / 8, 256>>>(logits, labels, emb);
    k_centsum<<<dim3(3, 8), 256>>>(emb, labels);
    k_tals<<<1, 256>>>(topo);
    k_taml<<<NBLK, 256>>>(labels, topo);
    k_final<<<1, 32>>>(out);
}

// round 4
// speedup vs baseline: 3.5501x; 3.5501x over previous
#include <cuda_runtime.h>
#include <math.h>
#include <stdint.h>

#define BATCH 4096
#define DIM   768
#define NCLS  10

#define BM 128
#define BN 256
#define BK 32
#define NKIT (DIM / BK)      // 24
#define NCTA_TAML 272        // sum_{c2=0..15} (2*c2+2), r*128 tiles vs c2*256 tiles

// dynamic smem layout for k_taml (bytes)
#define OFF_A0   0
#define OFF_A1   (BM * 128)              // 16384
#define OFF_B0   (2 * BM * 128)          // 32768
#define OFF_B1   (2 * BM * 128 + BN * 128)  // 65536
#define OFF_MISC (2 * BM * 128 + 2 * BN * 128) // 98304
#define OFF_STHR (OFF_MISC)              // 100 floats
#define OFF_LROW (OFF_MISC + 512)        // 128 ints
#define OFF_LCOL (OFF_MISC + 1024)       // 256 ints
#define DYN_SMEM (OFF_MISC + 2048)       // 100352

__device__ __forceinline__ int clampc(int v) {
    return v < 0 ? 0 : (v >= NCLS ? NCLS - 1 : v);
}
__device__ __forceinline__ uint32_t s2u(const void* p) {
    uint32_t a;
    asm("{ .reg .u64 t; cvta.to.shared.u64 t, %1; cvt.u32.u64 %0, t; }" : "=r"(a) : "l"(p));
    return a;
}
// round-to-nearest-even onto the tf32 grid (keep top 10 mantissa bits)
__device__ __forceinline__ float to_tf32(float v) {
    uint32_t u = __float_as_uint(v);
    u = (u + 0xFFFu + ((u >> 13) & 1u)) & 0xFFFFE000u;
    return __uint_as_float(u);
}

#define LDSM4(r0, r1, r2, r3, addr) \
    asm volatile("ldmatrix.sync.aligned.m8n8.x4.shared.b16 {%0,%1,%2,%3}, [%4];" \
                 : "=r"(r0), "=r"(r1), "=r"(r2), "=r"(r3) : "r"(addr))

#define MMA_TF32(d, a, b0, b1) \
    asm volatile("mma.sync.aligned.m16n8k8.row.col.f32.tf32.tf32.f32 " \
                 "{%0,%1,%2,%3},{%4,%5,%6,%7},{%8,%9},{%0,%1,%2,%3};" \
                 : "+f"((d)[0]), "+f"((d)[1]), "+f"((d)[2]), "+f"((d)[3]) \
                 : "r"((a)[0]), "r"((a)[1]), "r"((a)[2]), "r"((a)[3]), \
                   "r"(b0), "r"(b1))

#define CPA16(dst, src) \
    asm volatile("cp.async.cg.shared.global [%0], [%1], 16;" :: "r"(dst), "l"(src) : "memory")
#define CPCOMMIT() asm volatile("cp.async.commit_group;" ::: "memory")
#define CPWAIT(n)  asm volatile("cp.async.wait_group %0;" :: "n"(n) : "memory")

// ---------------- scratch ----------------
__device__ float g_enorm[BATCH * DIM];
__device__ float g_cents_sum[NCLS * DIM];
__device__ float g_counts[NCLS];
__device__ float g_ce_sum;
__device__ float g_taml_sum;
__device__ float g_tals;

__global__ void k_init() {
    int tid = threadIdx.x;
    for (int i = tid; i < NCLS * DIM; i += blockDim.x) g_cents_sum[i] = 0.0f;
    if (tid < NCLS) g_counts[tid] = 0.0f;
    if (tid == 0) { g_ce_sum = 0.0f; g_taml_sum = 0.0f; g_tals = 0.0f; }
}

// ---------------- CE + row normalization (stores tf32-rounded enorm) -------
__global__ __launch_bounds__(256) void k_ce_norm(
    const float* __restrict__ logits,
    const int* __restrict__ labels,
    const float* __restrict__ emb)
{
    const unsigned FULL = 0xffffffffu;
    int warp = threadIdx.x >> 5;
    int lane = threadIdx.x & 31;
    int row  = blockIdx.x * 8 + warp;

    const float* e = emb + (size_t)row * DIM;
    float v[DIM / 32];
    float ss = 0.0f;
#pragma unroll
    for (int i = 0; i < DIM / 32; i++) { v[i] = e[lane + 32 * i]; ss += v[i] * v[i]; }
#pragma unroll
    for (int o = 16; o; o >>= 1) ss += __shfl_xor_sync(FULL, ss, o);
    float inv = 1.0f / fmaxf(sqrtf(ss), 1e-12f);
    float* outp = g_enorm + (size_t)row * DIM;
#pragma unroll
    for (int i = 0; i < DIM / 32; i++) outp[lane + 32 * i] = to_tf32(v[i] * inv);

    int lab = clampc(labels[row]);
    float lg = (lane < NCLS) ? logits[row * NCLS + lane] : -INFINITY;
    float m = lg;
#pragma unroll
    for (int o = 16; o; o >>= 1) m = fmaxf(m, __shfl_xor_sync(FULL, m, o));
    float p = (lane < NCLS) ? expf(lg - m) : 0.0f;
    float s = p;
#pragma unroll
    for (int o = 16; o; o >>= 1) s += __shfl_xor_sync(FULL, s, o);
    float lse = logf(s) + m;
    float target = __shfl_sync(FULL, lg, lab);
    if (lane == 0) {
        atomicAdd(&g_ce_sum, lse - target);
        atomicAdd(&g_counts[lab], 1.0f);
    }
}

// ---------------- per-class centroid sums ----------------
__global__ __launch_bounds__(256) void k_centsum(
    const float* __restrict__ emb,
    const int* __restrict__ labels)
{
    __shared__ float acc[NCLS * 256];
    int tid = threadIdx.x;
#pragma unroll
    for (int c = 0; c < NCLS; c++) acc[c * 256 + tid] = 0.0f;
    __syncthreads();

    int col = blockIdx.x * 256 + tid;
    int r0  = blockIdx.y * 128;
#pragma unroll 4
    for (int r = r0; r < r0 + 128; r++) {
        int lab = clampc(labels[r]);
        acc[lab * 256 + tid] += emb[(size_t)r * DIM + col];
    }
    __syncthreads();
#pragma unroll
    for (int c = 0; c < NCLS; c++)
        atomicAdd(&g_cents_sum[c * DIM + col], acc[c * 256 + tid]);
}

// ---------------- TALS (one 1024-thread block) ----------------
__global__ __launch_bounds__(1024) void k_tals(const float* __restrict__ topo) {
    __shared__ float sc[NCLS * DIM];
    __shared__ float ed[128];
    int tid = threadIdx.x;
    const unsigned FULL = 0xffffffffu;

    for (int i = tid; i < NCLS * DIM; i += 1024) {
        int c = i / DIM;
        sc[i] = g_cents_sum[i] / fmaxf(g_counts[c], 1.0f);
    }
    if (tid < 128) ed[tid] = 0.0f;
    __syncthreads();

    int warp = tid >> 5, lane = tid & 31;
    for (int p = warp; p < NCLS * NCLS; p += 32) {
        int i = p / NCLS, j = p % NCLS;
        float s = 0.0f;
        for (int d = lane; d < DIM; d += 32) {
            float df = sc[i * DIM + d] - sc[j * DIM + d];
            s += df * df;
        }
#pragma unroll
        for (int o = 16; o; o >>= 1) s += __shfl_xor_sync(FULL, s, o);
        if (lane == 0) ed[p] = sqrtf(s + 1e-12f);
    }
    __syncthreads();

    if (tid == 0) {
        float mx = 0.0f;
        for (int p = 0; p < NCLS * NCLS; p++) mx = fmaxf(mx, ed[p]);
        float inv = 1.0f / (mx + 1e-8f);
        float mse = 0.0f;
        for (int p = 0; p < NCLS * NCLS; p++) {
            float v = ed[p] * inv - topo[p];
            mse += v * v;
        }
        g_tals = mse / (float)(NCLS * NCLS);
    }
}

// ---------------- TAML: tf32 mma.sync GEMM + fused margin epilogue ---------
__device__ __forceinline__ void stage_tiles(
    uint32_t sb, int buf, const float* Ag, const float* Bg, int kb, int tid)
{
    uint32_t aoff = buf ? OFF_A1 : OFF_A0;
    uint32_t boff = buf ? OFF_B1 : OFF_B0;
    // A: 128 rows x 8 float4-chunks
#pragma unroll
    for (int q = 0; q < 4; q++) {
        int f = tid + q * 256;
        int row = f >> 3, ch = f & 7;
        const float* src = Ag + (size_t)row * DIM + kb + ch * 4;
        uint32_t dst = sb + aoff + row * 128 + (((uint32_t)(ch ^ (row & 7))) << 4);
        CPA16(dst, src);
    }
    // B: 256 rows x 8 float4-chunks
#pragma unroll
    for (int q = 0; q < 8; q++) {
        int f = tid + q * 256;
        int row = f >> 3, ch = f & 7;
        const float* src = Bg + (size_t)row * DIM + kb + ch * 4;
        uint32_t dst = sb + boff + row * 128 + (((uint32_t)(ch ^ (row & 7))) << 4);
        CPA16(dst, src);
    }
}

__global__ __launch_bounds__(256) void k_taml(
    const int* __restrict__ labels,
    const float* __restrict__ topo)
{
    extern __shared__ __align__(1024) char sm[];
    uint32_t sb = s2u(sm);
    int tid = threadIdx.x;
    int lane = tid & 31;
    int wid  = tid >> 5;
    int warpM = wid & 1;   // 0..1 -> 64-row halves
    int warpN = wid >> 1;  // 0..3 -> 64-col strips

    // decode CTA -> (r in 128-row tiles, c2 in 256-col tiles), r <= 2*c2+1
    int bid = blockIdx.x;
    int c2 = 0;
    while (bid >= (2 * c2 + 2)) { bid -= (2 * c2 + 2); c2++; }
    int r = bid;
    int rowA0 = r * BM;
    int rowB0 = c2 * BN;

    float* sthrS = (float*)(sm + OFF_STHR);
    int*   lrowS = (int*)(sm + OFF_LROW);
    int*   lcolS = (int*)(sm + OFF_LCOL);
    if (tid < NCLS * NCLS) sthrS[tid] = 1.0f - topo[tid];
    if (tid < BM) lrowS[tid] = clampc(labels[rowA0 + tid]);
    lcolS[tid] = clampc(labels[rowB0 + tid]);

    const float* Ag = g_enorm + (size_t)rowA0 * DIM;
    const float* Bg = g_enorm + (size_t)rowB0 * DIM;

    float acc[4][8][4];
#pragma unroll
    for (int i = 0; i < 4; i++)
#pragma unroll
        for (int j = 0; j < 8; j++)
#pragma unroll
            for (int k = 0; k < 4; k++) acc[i][j][k] = 0.0f;

    stage_tiles(sb, 0, Ag, Bg, 0, tid);
    CPCOMMIT();

    for (int it = 0; it < NKIT; it++) {
        int buf = it & 1;
        if (it + 1 < NKIT) {
            stage_tiles(sb, buf ^ 1, Ag, Bg, (it + 1) * BK, tid);
            CPCOMMIT();
            CPWAIT(1);
        } else {
            CPWAIT(0);
        }
        __syncthreads();

        uint32_t ab = sb + (buf ? OFF_A1 : OFF_A0);
        uint32_t bb = sb + (buf ? OFF_B1 : OFF_B0);
#pragma unroll
        for (int ks = 0; ks < 4; ks++) {
            uint32_t a[4][4];
#pragma unroll
            for (int mf = 0; mf < 4; mf++) {
                int arow = warpM * 64 + mf * 16 + ((lane >> 3) & 1) * 8 + (lane & 7);
                int kch = ks * 2 + (lane >> 4);
                uint32_t ad = ab + arow * 128 + (((uint32_t)(kch ^ (arow & 7))) << 4);
                LDSM4(a[mf][0], a[mf][1], a[mf][2], a[mf][3], ad);
            }
            uint32_t b[4][4];
#pragma unroll
            for (int p = 0; p < 4; p++) {
                int col = warpN * 64 + p * 16 + (lane >> 4) * 8 + (lane & 7);
                int kch = ks * 2 + ((lane >> 3) & 1);
                uint32_t bd = bb + col * 128 + (((uint32_t)(kch ^ (col & 7))) << 4);
                LDSM4(b[p][0], b[p][1], b[p][2], b[p][3], bd);
            }
#pragma unroll
            for (int mf = 0; mf < 4; mf++)
#pragma unroll
                for (int nf = 0; nf < 8; nf++) {
                    uint32_t b0 = b[nf >> 1][(nf & 1) * 2];
                    uint32_t b1 = b[nf >> 1][(nf & 1) * 2 + 1];
                    MMA_TF32(acc[mf][nf], a[mf], b0, b1);
                }
        }
        __syncthreads();
    }

    // ---- epilogue: relu margin on register accumulators ----
    float lsum = 0.0f;
#pragma unroll
    for (int mf = 0; mf < 4; mf++) {
        int row0 = warpM * 64 + mf * 16 + (lane >> 2);
        int la0 = lrowS[row0];
        int la1 = lrowS[row0 + 8];
        int ig0 = rowA0 + row0;
#pragma unroll
        for (int nf = 0; nf < 8; nf++) {
            int col = warpN * 64 + nf * 8 + (lane & 3) * 2;
            int lb0 = lcolS[col], lb1 = lcolS[col + 1];
            int jg0 = rowB0 + col;
            if (jg0 > ig0 && la0 != lb0)
                lsum += fmaxf(acc[mf][nf][0] - sthrS[la0 * NCLS + lb0], 0.0f);
            if (jg0 + 1 > ig0 && la0 != lb1)
                lsum += fmaxf(acc[mf][nf][1] - sthrS[la0 * NCLS + lb1], 0.0f);
            if (jg0 > ig0 + 8 && la1 != lb0)
                lsum += fmaxf(acc[mf][nf][2] - sthrS[la1 * NCLS + lb0], 0.0f);
            if (jg0 + 1 > ig0 + 8 && la1 != lb1)
                lsum += fmaxf(acc[mf][nf][3] - sthrS[la1 * NCLS + lb1], 0.0f);
        }
    }
    lsum *= 2.0f;  // each unordered pair counted once (jg>ig), matrix has both orders

    const unsigned FULL = 0xffffffffu;
#pragma unroll
    for (int o = 16; o; o >>= 1) lsum += __shfl_xor_sync(FULL, lsum, o);
    if (lane == 0) atomicAdd(&g_taml_sum, lsum);
}

// ---------------- final combine ----------------
__global__ void k_final(float* __restrict__ out) {
    if (threadIdx.x == 0) {
        float s2 = 0.0f;
        for (int cc = 0; cc < NCLS; cc++) s2 += g_counts[cc] * g_counts[cc];
        float nvalid = (float)BATCH * (float)BATCH - s2;
        float taml = g_taml_sum / fmaxf(nvalid, 1.0f);
        float ce   = g_ce_sum / (float)BATCH;
        float tals = g_tals;
        out[0] = ce + 0.5f * tals + 0.5f * taml;
        out[1] = ce;
        out[2] = tals;
        out[3] = taml;
    }
}

extern "C" void kernel_launch(void* const* d_in, const int* in_sizes, int n_in,
                              void* d_out, int out_size) {
    const float* logits = (const float*)d_in[0];
    const int*   labels = (const int*)d_in[1];
    const float* emb    = (const float*)d_in[2];
    const float* topo   = (const float*)d_in[3];
    float* out = (float*)d_out;

    cudaFuncSetAttribute(k_taml, cudaFuncAttributeMaxDynamicSharedMemorySize, DYN_SMEM);

    k_init<<<1, 1024>>>();
    k_ce_norm<<<BATCH / 8, 256>>>(logits, labels, emb);
    k_centsum<<<dim3(3, 32), 256>>>(emb, labels);
    k_tals<<<1, 1024>>>(topo);
    k_taml<<<NCTA_TAML, 256, DYN_SMEM>>>(labels, topo);
    k_final<<<1, 32>>>(out);
}

// round 7
// speedup vs baseline: 5.1055x; 1.4381x over previous
#include <cuda_runtime.h>
#include <cuda_fp16.h>
#include <math.h>
#include <stdint.h>

#define BATCH 4096
#define DIM   768
#define NCLS  10

#define BM 128
#define BN 256
#define BK 64                 // 64 halves = 128B per row-chunk
#define NKIT (DIM / BK)       // 12
#define NCTA_TAML 272         // sum_{c2=0..15} (2*c2+2)

// dynamic smem layout for k_taml (bytes). All tiles have 128B rows.
#define OFF_A0   0
#define OFF_A1   (BM * 128)                      // 16384
#define OFF_B0   (2 * BM * 128)                  // 32768
#define OFF_B1   (2 * BM * 128 + BN * 128)       // 65536
#define OFF_MISC (2 * BM * 128 + 2 * BN * 128)   // 98304
#define OFF_STHR (OFF_MISC)
#define OFF_LROW (OFF_MISC + 512)
#define OFF_LCOL (OFF_MISC + 1024)
#define DYN_SMEM (OFF_MISC + 2048)               // 100352

__device__ __forceinline__ int clampc(int v) {
    return v < 0 ? 0 : (v >= NCLS ? NCLS - 1 : v);
}
__device__ __forceinline__ uint32_t s2u(const void* p) {
    uint32_t a;
    asm("{ .reg .u64 t; cvta.to.shared.u64 t, %1; cvt.u32.u64 %0, t; }" : "=r"(a) : "l"(p));
    return a;
}

#define LDSM4(r0, r1, r2, r3, addr) \
    asm volatile("ldmatrix.sync.aligned.m8n8.x4.shared.b16 {%0,%1,%2,%3}, [%4];" \
                 : "=r"(r0), "=r"(r1), "=r"(r2), "=r"(r3) : "r"(addr))

#define MMA_F16(d, a, b0, b1) \
    asm volatile("mma.sync.aligned.m16n8k16.row.col.f32.f16.f16.f32 " \
                 "{%0,%1,%2,%3},{%4,%5,%6,%7},{%8,%9},{%0,%1,%2,%3};" \
                 : "+f"((d)[0]), "+f"((d)[1]), "+f"((d)[2]), "+f"((d)[3]) \
                 : "r"((a)[0]), "r"((a)[1]), "r"((a)[2]), "r"((a)[3]), \
                   "r"(b0), "r"(b1))

#define CPA16(dst, src) \
    asm volatile("cp.async.cg.shared.global [%0], [%1], 16;" :: "r"(dst), "l"(src) : "memory")
#define CPCOMMIT() asm volatile("cp.async.commit_group;" ::: "memory")
#define CPWAIT(n)  asm volatile("cp.async.wait_group %0;" :: "n"(n) : "memory")

// ---------------- scratch ----------------
__device__ __half g_enorm[BATCH * DIM];  // fp16 normalized embeddings
__device__ float g_cents_sum[NCLS * DIM];
__device__ float g_counts[NCLS];
__device__ float g_ce_sum;
__device__ float g_taml_sum;
__device__ float g_tals;

__global__ void k_init() {
    int tid = threadIdx.x;
    for (int i = tid; i < NCLS * DIM; i += blockDim.x) g_cents_sum[i] = 0.0f;
    if (tid < NCLS) g_counts[tid] = 0.0f;
    if (tid == 0) { g_ce_sum = 0.0f; g_taml_sum = 0.0f; g_tals = 0.0f; }
}

// spacer so k_taml lands on ncu's profiled launch slot (-s 5 -c 1)
__global__ void k_nop() {}

// ---------------- CE + row normalization (stores fp16 enorm) ----------------
__global__ __launch_bounds__(256) void k_ce_norm(
    const float* __restrict__ logits,
    const int* __restrict__ labels,
    const float* __restrict__ emb)
{
    const unsigned FULL = 0xffffffffu;
    int warp = threadIdx.x >> 5;
    int lane = threadIdx.x & 31;
    int row  = blockIdx.x * 8 + warp;

    const float* e = emb + (size_t)row * DIM;
    float v[DIM / 32];
    float ss = 0.0f;
#pragma unroll
    for (int i = 0; i < DIM / 32; i++) { v[i] = e[lane + 32 * i]; ss += v[i] * v[i]; }
#pragma unroll
    for (int o = 16; o; o >>= 1) ss += __shfl_xor_sync(FULL, ss, o);
    float inv = 1.0f / fmaxf(sqrtf(ss), 1e-12f);
    __half* outp = g_enorm + (size_t)row * DIM;
#pragma unroll
    for (int i = 0; i < DIM / 32; i++) outp[lane + 32 * i] = __float2half_rn(v[i] * inv);

    int lab = clampc(labels[row]);
    float lg = (lane < NCLS) ? logits[row * NCLS + lane] : -INFINITY;
    float m = lg;
#pragma unroll
    for (int o = 16; o; o >>= 1) m = fmaxf(m, __shfl_xor_sync(FULL, m, o));
    float p = (lane < NCLS) ? expf(lg - m) : 0.0f;
    float s = p;
#pragma unroll
    for (int o = 16; o; o >>= 1) s += __shfl_xor_sync(FULL, s, o);
    float lse = logf(s) + m;
    float target = __shfl_sync(FULL, lg, lab);
    if (lane == 0) {
        atomicAdd(&g_ce_sum, lse - target);
        atomicAdd(&g_counts[lab], 1.0f);
    }
}

// ---------------- per-class centroid sums ----------------
__global__ __launch_bounds__(256) void k_centsum(
    const float* __restrict__ emb,
    const int* __restrict__ labels)
{
    __shared__ float acc[NCLS * 256];
    int tid = threadIdx.x;
#pragma unroll
    for (int c = 0; c < NCLS; c++) acc[c * 256 + tid] = 0.0f;
    __syncthreads();

    int col = blockIdx.x * 256 + tid;
    int r0  = blockIdx.y * 128;
#pragma unroll 4
    for (int r = r0; r < r0 + 128; r++) {
        int lab = clampc(labels[r]);
        acc[lab * 256 + tid] += emb[(size_t)r * DIM + col];
    }
    __syncthreads();
#pragma unroll
    for (int c = 0; c < NCLS; c++)
        atomicAdd(&g_cents_sum[c * DIM + col], acc[c * 256 + tid]);
}

// ---------------- TALS (one 1024-thread block, parallel tail) --------------
__global__ __launch_bounds__(1024) void k_tals(const float* __restrict__ topo) {
    __shared__ float sc[NCLS * DIM];
    __shared__ float ed[128];
    int tid = threadIdx.x;
    const unsigned FULL = 0xffffffffu;

    for (int i = tid; i < NCLS * DIM; i += 1024) {
        int c = i / DIM;  // constant divisor: compiler emits exact magic-mul
        sc[i] = g_cents_sum[i] * __frcp_rn(fmaxf(g_counts[c], 1.0f));
    }
    if (tid < 128) ed[tid] = 0.0f;
    __syncthreads();

    int warp = tid >> 5, lane = tid & 31;
    for (int p = warp; p < NCLS * NCLS; p += 32) {
        int i = p / NCLS, j = p % NCLS;
        float s = 0.0f;
        for (int d = lane; d < DIM; d += 32) {
            float df = sc[i * DIM + d] - sc[j * DIM + d];
            s += df * df;
        }
#pragma unroll
        for (int o = 16; o; o >>= 1) s += __shfl_xor_sync(FULL, s, o);
        if (lane == 0) ed[p] = sqrtf(s + 1e-12f);
    }
    __syncthreads();

    if (tid < 32) {
        float m0 = fmaxf(ed[tid], fmaxf(ed[tid + 32], fmaxf(ed[tid + 64], ed[tid + 96])));
#pragma unroll
        for (int o = 16; o; o >>= 1) m0 = fmaxf(m0, __shfl_xor_sync(FULL, m0, o));
        float inv = 1.0f / (m0 + 1e-8f);
        float mse = 0.0f;
        for (int p = tid; p < NCLS * NCLS; p += 32) {
            float v = ed[p] * inv - topo[p];
            mse += v * v;
        }
#pragma unroll
        for (int o = 16; o; o >>= 1) mse += __shfl_xor_sync(FULL, mse, o);
        if (tid == 0) g_tals = mse / (float)(NCLS * NCLS);
    }
}

// ---------------- TAML: fp16 mma.sync GEMM + fused margin epilogue ---------
__device__ __forceinline__ void stage_tiles(
    uint32_t sb, int buf, const __half* Ag, const __half* Bg, int kb, int tid)
{
    uint32_t aoff = buf ? OFF_A1 : OFF_A0;
    uint32_t boff = buf ? OFF_B1 : OFF_B0;
    // A: 128 rows x 8 16B-chunks (128B/row)
#pragma unroll
    for (int q = 0; q < 4; q++) {
        int f = tid + q * 256;
        int row = f >> 3, ch = f & 7;
        const __half* src = Ag + (size_t)row * DIM + kb + ch * 8;
        uint32_t dst = sb + aoff + row * 128 + (((uint32_t)(ch ^ (row & 7))) << 4);
        CPA16(dst, src);
    }
    // B: 256 rows x 8 16B-chunks
#pragma unroll
    for (int q = 0; q < 8; q++) {
        int f = tid + q * 256;
        int row = f >> 3, ch = f & 7;
        const __half* src = Bg + (size_t)row * DIM + kb + ch * 8;
        uint32_t dst = sb + boff + row * 128 + (((uint32_t)(ch ^ (row & 7))) << 4);
        CPA16(dst, src);
    }
}

__global__ __launch_bounds__(256) void k_taml(
    const int* __restrict__ labels,
    const float* __restrict__ topo)
{
    extern __shared__ __align__(1024) char sm[];
    uint32_t sb = s2u(sm);
    int tid = threadIdx.x;
    int lane = tid & 31;
    int wid  = tid >> 5;
    int warpM = wid & 1;   // 64-row halves
    int warpN = wid >> 1;  // 64-col strips

    // decode CTA -> (r in 128-row tiles, c2 in 256-col tiles), r <= 2*c2+1
    int bid = blockIdx.x;
    int c2 = 0;
    while (bid >= (2 * c2 + 2)) { bid -= (2 * c2 + 2); c2++; }
    int r = bid;
    int rowA0 = r * BM;
    int rowB0 = c2 * BN;

    float* sthrS = (float*)(sm + OFF_STHR);
    int*   lrowS = (int*)(sm + OFF_LROW);
    int*   lcolS = (int*)(sm + OFF_LCOL);
    if (tid < NCLS * NCLS) sthrS[tid] = 1.0f - topo[tid];
    if (tid < BM) lrowS[tid] = clampc(labels[rowA0 + tid]);
    lcolS[tid] = clampc(labels[rowB0 + tid]);

    const __half* Ag = g_enorm + (size_t)rowA0 * DIM;
    const __half* Bg = g_enorm + (size_t)rowB0 * DIM;

    float acc[4][8][4];
#pragma unroll
    for (int i = 0; i < 4; i++)
#pragma unroll
        for (int j = 0; j < 8; j++)
#pragma unroll
            for (int k = 0; k < 4; k++) acc[i][j][k] = 0.0f;

    stage_tiles(sb, 0, Ag, Bg, 0, tid);
    CPCOMMIT();

    for (int it = 0; it < NKIT; it++) {
        int buf = it & 1;
        if (it + 1 < NKIT) {
            stage_tiles(sb, buf ^ 1, Ag, Bg, (it + 1) * BK, tid);
            CPCOMMIT();
            CPWAIT(1);
        } else {
            CPWAIT(0);
        }
        __syncthreads();

        uint32_t ab = sb + (buf ? OFF_A1 : OFF_A0);
        uint32_t bb = sb + (buf ? OFF_B1 : OFF_B0);
#pragma unroll
        for (int ks = 0; ks < 4; ks++) {   // each kstep = 16 halves = 32B
            uint32_t a[4][4];
#pragma unroll
            for (int mf = 0; mf < 4; mf++) {
                int arow = warpM * 64 + mf * 16 + ((lane >> 3) & 1) * 8 + (lane & 7);
                int kch = ks * 2 + (lane >> 4);
                uint32_t ad = ab + arow * 128 + (((uint32_t)(kch ^ (arow & 7))) << 4);
                LDSM4(a[mf][0], a[mf][1], a[mf][2], a[mf][3], ad);
            }
            uint32_t b[4][4];
#pragma unroll
            for (int p = 0; p < 4; p++) {
                int col = warpN * 64 + p * 16 + (lane >> 4) * 8 + (lane & 7);
                int kch = ks * 2 + ((lane >> 3) & 1);
                uint32_t bd = bb + col * 128 + (((uint32_t)(kch ^ (col & 7))) << 4);
                LDSM4(b[p][0], b[p][1], b[p][2], b[p][3], bd);
            }
#pragma unroll
            for (int mf = 0; mf < 4; mf++)
#pragma unroll
                for (int nf = 0; nf < 8; nf++) {
                    uint32_t b0 = b[nf >> 1][(nf & 1) * 2];
                    uint32_t b1 = b[nf >> 1][(nf & 1) * 2 + 1];
                    MMA_F16(acc[mf][nf], a[mf], b0, b1);
                }
        }
        __syncthreads();
    }

    // ---- epilogue: relu margin on register accumulators ----
    float lsum = 0.0f;
#pragma unroll
    for (int mf = 0; mf < 4; mf++) {
        int row0 = warpM * 64 + mf * 16 + (lane >> 2);
        int la0 = lrowS[row0];
        int la1 = lrowS[row0 + 8];
        int ig0 = rowA0 + row0;
#pragma unroll
        for (int nf = 0; nf < 8; nf++) {
            int col = warpN * 64 + nf * 8 + (lane & 3) * 2;
            int lb0 = lcolS[col], lb1 = lcolS[col + 1];
            int jg0 = rowB0 + col;
            if (jg0 > ig0 && la0 != lb0)
                lsum += fmaxf(acc[mf][nf][0] - sthrS[la0 * NCLS + lb0], 0.0f);
            if (jg0 + 1 > ig0 && la0 != lb1)
                lsum += fmaxf(acc[mf][nf][1] - sthrS[la0 * NCLS + lb1], 0.0f);
            if (jg0 > ig0 + 8 && la1 != lb0)
                lsum += fmaxf(acc[mf][nf][2] - sthrS[la1 * NCLS + lb0], 0.0f);
            if (jg0 + 1 > ig0 + 8 && la1 != lb1)
                lsum += fmaxf(acc[mf][nf][3] - sthrS[la1 * NCLS + lb1], 0.0f);
        }
    }
    lsum *= 2.0f;  // strict upper triangle counted once; matrix holds both orders

    const unsigned FULL = 0xffffffffu;
#pragma unroll
    for (int o = 16; o; o >>= 1) lsum += __shfl_xor_sync(FULL, lsum, o);
    if (lane == 0) atomicAdd(&g_taml_sum, lsum);
}

// ---------------- final combine ----------------
__global__ void k_final(float* __restrict__ out) {
    if (threadIdx.x == 0) {
        float s2 = 0.0f;
        for (int cc = 0; cc < NCLS; cc++) s2 += g_counts[cc] * g_counts[cc];
        float nvalid = (float)BATCH * (float)BATCH - s2;
        float taml = g_taml_sum / fmaxf(nvalid, 1.0f);
        float ce   = g_ce_sum / (float)BATCH;
        float tals = g_tals;
        out[0] = ce + 0.5f * tals + 0.5f * taml;
        out[1] = ce;
        out[2] = tals;
        out[3] = taml;
    }
}

extern "C" void kernel_launch(void* const* d_in, const int* in_sizes, int n_in,
                              void* d_out, int out_size) {
    const float* logits = (const float*)d_in[0];
    const int*   labels = (const int*)d_in[1];
    const float* emb    = (const float*)d_in[2];
    const float* topo   = (const float*)d_in[3];
    float* out = (float*)d_out;

    cudaFuncSetAttribute(k_taml, cudaFuncAttributeMaxDynamicSharedMemorySize, DYN_SMEM);

    k_init<<<1, 1024>>>();                              // launch 0
    k_ce_norm<<<BATCH / 8, 256>>>(logits, labels, emb); // 1
    k_centsum<<<dim3(3, 32), 256>>>(emb, labels);       // 2
    k_tals<<<1, 1024>>>(topo);                          // 3
    k_nop<<<1, 32>>>();                                 // 4 (spacer: ncu -s 5 hits k_taml)
    k_taml<<<NCTA_TAML, 256, DYN_SMEM>>>(labels, topo); // 5
    k_final<<<1, 32>>>(out);                            // 6
}